// round 2
// baseline (speedup 1.0000x reference)
#include <cuda_runtime.h>
#include <cuda_bf16.h>
#include <cstdint>

// ---------------------------------------------------------------------------
// GCN: 4 layers. Per layer: h = X@W ; out = b + dinv^2*h + sum_{e:dst=i} norm_e*h[src_e]
// relu folded into next GEMM's input load. Layer 4 width 40 (padded to 64 for GEMM).
// Outputs: d_out[0 : N*40] = logits, d_out[N*40 : N*40+N*128] = relu(layer3 agg).
// ---------------------------------------------------------------------------

#define N_NODES 100000
#define N_EDGES 1600000

__device__ float g_bufA[(size_t)N_NODES * 128];   // GEMM output h
__device__ float g_bufB[(size_t)N_NODES * 128];   // aggregation output
__device__ float g_dinv[N_NODES];
__device__ float g_W4p[128 * 64];

// ---------------- degree / dinv ----------------
__global__ void k_set_one(float* d, int n) {
    int i = blockIdx.x * blockDim.x + threadIdx.x;
    if (i < n) d[i] = 1.0f;   // self-loop contributes 1 to degree
}

__global__ void k_deg(const int* __restrict__ dst, float* deg, int E) {
    int e = blockIdx.x * blockDim.x + threadIdx.x;
    if (e < E) atomicAdd(&deg[dst[e]], 1.0f);
}

__global__ void k_rsqrt(float* d, int n) {
    int i = blockIdx.x * blockDim.x + threadIdx.x;
    if (i < n) d[i] = rsqrtf(d[i]);
}

// ---------------- pad W4 (128x40 -> 128x64, zeros) ----------------
__global__ void k_pad_w4(const float* __restrict__ W4, float* W4p) {
    int t = blockIdx.x * blockDim.x + threadIdx.x;   // 128*64 threads
    if (t < 128 * 64) {
        int k = t >> 6, c = t & 63;
        W4p[t] = (c < 40) ? W4[k * 40 + c] : 0.0f;
    }
}

// ---------------- GEMM: Y[N,NCOL] = (relu?)X[N,128] @ W[128,NCOL] ----------------
template <int NCOL, bool RELU>
__global__ void __launch_bounds__(256, 2)
k_gemm(const float* __restrict__ X, const float* __restrict__ W,
       float* __restrict__ Y, int Nrows) {
    constexpr int CG = NCOL / 8;      // column groups (threads along N)
    constexpr int RG = 256 / CG;      // row groups
    constexpr int TILE_M = RG * 8;
    __shared__ float xs[TILE_M * 32];
    __shared__ float ws[32 * NCOL];

    int tid = threadIdx.x;
    int tc = tid % CG;
    int tr = tid / CG;
    int c0 = tc * 8;
    int rowBase = blockIdx.x * TILE_M;

    float acc[8][8];
#pragma unroll
    for (int i = 0; i < 8; ++i)
#pragma unroll
        for (int j = 0; j < 8; ++j) acc[i][j] = 0.0f;

    for (int k0 = 0; k0 < 128; k0 += 32) {
        // --- stage W tile [32 x NCOL] (contiguous rows, coalesced) ---
        for (int idx = tid; idx < 32 * NCOL; idx += 256)
            ws[idx] = W[k0 * NCOL + idx];
        // --- stage X tile [TILE_M x 32] as float4 ---
        constexpr int NF4 = TILE_M * 8;     // float4 elements
#pragma unroll
        for (int j = 0; j < NF4 / 256; ++j) {
            int fi = tid + j * 256;
            int row = fi >> 3, kq = fi & 7;
            int gr = rowBase + row;
            float4 v = make_float4(0.f, 0.f, 0.f, 0.f);
            if (gr < Nrows)
                v = *(const float4*)&X[(size_t)gr * 128 + k0 + kq * 4];
            if (RELU) {
                v.x = fmaxf(v.x, 0.f); v.y = fmaxf(v.y, 0.f);
                v.z = fmaxf(v.z, 0.f); v.w = fmaxf(v.w, 0.f);
            }
            *(float4*)&xs[row * 32 + kq * 4] = v;
        }
        __syncthreads();
#pragma unroll
        for (int kk = 0; kk < 32; ++kk) {
            float a[8];
#pragma unroll
            for (int i = 0; i < 8; ++i) a[i] = xs[(tr * 8 + i) * 32 + kk];
            float4 b0 = *(const float4*)&ws[kk * NCOL + c0];
            float4 b1 = *(const float4*)&ws[kk * NCOL + c0 + 4];
            float bb[8] = {b0.x, b0.y, b0.z, b0.w, b1.x, b1.y, b1.z, b1.w};
#pragma unroll
            for (int i = 0; i < 8; ++i)
#pragma unroll
                for (int j = 0; j < 8; ++j)
                    acc[i][j] = fmaf(a[i], bb[j], acc[i][j]);
        }
        __syncthreads();
    }
    // --- store ---
#pragma unroll
    for (int i = 0; i < 8; ++i) {
        int gr = rowBase + tr * 8 + i;
        if (gr < Nrows) {
            float4 o0 = make_float4(acc[i][0], acc[i][1], acc[i][2], acc[i][3]);
            float4 o1 = make_float4(acc[i][4], acc[i][5], acc[i][6], acc[i][7]);
            *(float4*)&Y[(size_t)gr * NCOL + c0] = o0;
            *(float4*)&Y[(size_t)gr * NCOL + c0 + 4] = o1;
        }
    }
}

// ---------------- init: OUT = b + dinv^2 * H  (width 128) ----------------
__global__ void k_init128(const float* __restrict__ H, const float* __restrict__ b,
                          const float* __restrict__ dinv, float* __restrict__ OUT, int N) {
    int t = blockIdx.x * blockDim.x + threadIdx.x;   // N*32 float4 tasks
    if (t >= N * 32) return;
    int i = t >> 5, c4 = t & 31;
    float di = dinv[i];
    float sn = di * di;
    float4 h = ((const float4*)H)[t];
    float4 bv = ((const float4*)b)[c4];
    float4 o = make_float4(fmaf(sn, h.x, bv.x), fmaf(sn, h.y, bv.y),
                           fmaf(sn, h.z, bv.z), fmaf(sn, h.w, bv.w));
    ((float4*)OUT)[t] = o;
}

// ---------------- init layer4: d_out[i*40+..] = b4 + dinv^2 * H64 ----------------
__global__ void k_init40(const float* __restrict__ H64, const float* __restrict__ b4,
                         const float* __restrict__ dinv, float* __restrict__ OUT, int N) {
    int t = blockIdx.x * blockDim.x + threadIdx.x;   // N*10 float4 tasks
    if (t >= N * 10) return;
    int i = t / 10, q = t - i * 10;
    float di = dinv[i];
    float sn = di * di;
    float4 h = *(const float4*)&H64[(size_t)i * 64 + q * 4];
    float4 bv = ((const float4*)b4)[q];
    float4 o = make_float4(fmaf(sn, h.x, bv.x), fmaf(sn, h.y, bv.y),
                           fmaf(sn, h.z, bv.z), fmaf(sn, h.w, bv.w));
    *(float4*)&OUT[(size_t)i * 40 + q * 4] = o;
}

// ---------------- edge aggregation width 128: one warp per edge ----------------
__global__ void k_agg128(const float* __restrict__ H, float* __restrict__ OUT,
                         const int* __restrict__ src, const int* __restrict__ dst,
                         const float* __restrict__ dinv, int E) {
    int gw = (blockIdx.x * blockDim.x + threadIdx.x) >> 5;
    int lane = threadIdx.x & 31;
    if (gw >= E) return;
    int s = __ldg(&src[gw]);
    int d = __ldg(&dst[gw]);
    float nrm = __ldg(&dinv[s]) * __ldg(&dinv[d]);
    float4 v = ((const float4*)(H + (size_t)s * 128))[lane];
    v.x *= nrm; v.y *= nrm; v.z *= nrm; v.w *= nrm;
    float* op = OUT + (size_t)d * 128 + lane * 4;
    asm volatile("red.global.add.v4.f32 [%0], {%1,%2,%3,%4};"
                 :: "l"(op), "f"(v.x), "f"(v.y), "f"(v.z), "f"(v.w) : "memory");
}

// ---------------- edge aggregation width 40 (H stride 64): 10 float4/edge ----------
__global__ void k_agg40(const float* __restrict__ H64, float* __restrict__ OUT,
                        const int* __restrict__ src, const int* __restrict__ dst,
                        const float* __restrict__ dinv, int E) {
    int t = blockIdx.x * blockDim.x + threadIdx.x;
    if (t >= E * 10) return;
    int e = t / 10, q = t - e * 10;
    int s = __ldg(&src[e]);
    int d = __ldg(&dst[e]);
    float nrm = __ldg(&dinv[s]) * __ldg(&dinv[d]);
    float4 v = *(const float4*)&H64[(size_t)s * 64 + q * 4];
    v.x *= nrm; v.y *= nrm; v.z *= nrm; v.w *= nrm;
    float* op = OUT + (size_t)d * 40 + q * 4;
    asm volatile("red.global.add.v4.f32 [%0], {%1,%2,%3,%4};"
                 :: "l"(op), "f"(v.x), "f"(v.y), "f"(v.z), "f"(v.w) : "memory");
}

// ---------------- latent: d_out[N*40 + t] = relu(bufB) ----------------
__global__ void k_latent(const float* __restrict__ A, float* __restrict__ OUT, int N) {
    int t = blockIdx.x * blockDim.x + threadIdx.x;   // N*32 float4 tasks
    if (t >= N * 32) return;
    float4 v = ((const float4*)A)[t];
    v.x = fmaxf(v.x, 0.f); v.y = fmaxf(v.y, 0.f);
    v.z = fmaxf(v.z, 0.f); v.w = fmaxf(v.w, 0.f);
    ((float4*)OUT)[t] = v;
}

// ---------------------------------------------------------------------------
extern "C" void kernel_launch(void* const* d_in, const int* in_sizes, int n_in,
                              void* d_out, int out_size) {
    const float* x   = (const float*)d_in[0];
    const int*   ei  = (const int*)d_in[1];
    const float* W1  = (const float*)d_in[2];
    const float* b1  = (const float*)d_in[3];
    const float* W2  = (const float*)d_in[4];
    const float* b2  = (const float*)d_in[5];
    const float* W3  = (const float*)d_in[6];
    const float* b3  = (const float*)d_in[7];
    const float* W4  = (const float*)d_in[8];
    const float* b4  = (const float*)d_in[9];
    float* out = (float*)d_out;

    int N = in_sizes[0] / 128;
    int E = in_sizes[1] / 2;
    const int* src = ei;
    const int* dst = ei + E;

    float *bufA, *bufB, *dinv, *W4p;
    cudaGetSymbolAddress((void**)&bufA, g_bufA);
    cudaGetSymbolAddress((void**)&bufB, g_bufB);
    cudaGetSymbolAddress((void**)&dinv, g_dinv);
    cudaGetSymbolAddress((void**)&W4p,  g_W4p);

    // degrees -> dinv
    k_set_one<<<(N + 255) / 256, 256>>>(dinv, N);
    k_deg<<<(E + 255) / 256, 256>>>(dst, dinv, E);
    k_rsqrt<<<(N + 255) / 256, 256>>>(dinv, N);
    k_pad_w4<<<(128 * 64 + 255) / 256, 256>>>(W4, W4p);

    int gemm128_blocks = (N + 127) / 128;
    int gemm64_blocks  = (N + 255) / 256;
    int init128_blocks = (N * 32 + 255) / 256;
    int agg128_blocks  = ((E * 32) + 255) / 256;
    int agg40_blocks   = ((E * 10) + 255) / 256;
    int init40_blocks  = (N * 10 + 255) / 256;

    // Layer 1
    k_gemm<128, false><<<gemm128_blocks, 256>>>(x, W1, bufA, N);
    k_init128<<<init128_blocks, 256>>>(bufA, b1, dinv, bufB, N);
    k_agg128<<<agg128_blocks, 256>>>(bufA, bufB, src, dst, dinv, E);
    // Layer 2 (relu folded into GEMM load)
    k_gemm<128, true><<<gemm128_blocks, 256>>>(bufB, W2, bufA, N);
    k_init128<<<init128_blocks, 256>>>(bufA, b2, dinv, bufB, N);
    k_agg128<<<agg128_blocks, 256>>>(bufA, bufB, src, dst, dinv, E);
    // Layer 3
    k_gemm<128, true><<<gemm128_blocks, 256>>>(bufB, W3, bufA, N);
    k_init128<<<init128_blocks, 256>>>(bufA, b3, dinv, bufB, N);
    k_agg128<<<agg128_blocks, 256>>>(bufA, bufB, src, dst, dinv, E);
    // Latent output = relu(layer3 agg)
    k_latent<<<init128_blocks, 256>>>(bufB, out + (size_t)N * 40, N);
    // Layer 4: GEMM (relu on input) to padded 64-wide, then 40-wide aggregation
    k_gemm<64, true><<<gemm64_blocks, 256>>>(bufB, W4p, bufA, N);
    k_init40<<<init40_blocks, 256>>>(bufA, b4, dinv, out, N);
    k_agg40<<<agg40_blocks, 256>>>(bufA, out, src, dst, dinv, E);
}

// round 4
// speedup vs baseline: 1.5904x; 1.5904x over previous
#include <cuda_runtime.h>
#include <cuda_bf16.h>
#include <cstdint>

// ---------------------------------------------------------------------------
// GCN 4 layers. Per layer: h = X@W ; out_i = b + dinv_i^2*h_i + sum_e nrm_e*h[src_e]
// CSR built per launch (int deg -> scan -> scatter). Aggregation fused with
// bias/self-loop/relu, register accumulation, no atomics on features.
// GEMM uses packed fma.rn.f32x2 (2x fp32 throughput).
// Outputs: d_out[0:N*40] = logits, d_out[N*40:+N*128] = relu(layer3 agg).
// ---------------------------------------------------------------------------

#define N_NODES 100000
#define N_EDGES 1600000

__device__ float g_bufA[(size_t)N_NODES * 128];   // GEMM output h
__device__ float g_bufB[(size_t)N_NODES * 128];   // aggregation output
__device__ float g_dinv[N_NODES];
__device__ float g_W4p[128 * 64];
__device__ int   g_cnt[N_NODES];
__device__ int   g_rows[N_NODES];
__device__ int   g_cur[N_NODES];
__device__ int   g_bsum[512];
__device__ int   g_csrc[N_EDGES];

// ---------------- packed f32x2 helpers ----------------
#define FFMA2(c, a, b) asm("fma.rn.f32x2 %0, %1, %2, %0;" : "+l"(c) : "l"(a), "l"(b))
#define DUP2(d, s)     asm("mov.b64 %0, {%1, %1};" : "=l"(d) : "r"(__float_as_uint(s)))
#define UNPK2(lo, hi, v) asm("mov.b64 {%0, %1}, %2;" : "=r"(lo), "=r"(hi) : "l"(v))

// ---------------- CSR build ----------------
__global__ void k_zero_int(int* p, int n) {
    int i = blockIdx.x * blockDim.x + threadIdx.x;
    if (i < n) p[i] = 0;
}

__global__ void k_deg_int(const int* __restrict__ dst, int* cnt, int E) {
    int e = blockIdx.x * blockDim.x + threadIdx.x;
    if (e < E) atomicAdd(&cnt[dst[e]], 1);
}

__global__ void k_dinv(const int* __restrict__ cnt, float* dinv, int n) {
    int i = blockIdx.x * blockDim.x + threadIdx.x;
    if (i < n) dinv[i] = rsqrtf((float)cnt[i] + 1.0f);   // +1 self loop
}

__global__ void k_scan1(const int* __restrict__ cnt, int* part, int* bsum, int n) {
    __shared__ int sh[512];
    int tx = threadIdx.x;
    int i = blockIdx.x * 512 + tx;
    int v = (i < n) ? cnt[i] : 0;
    sh[tx] = v;
    __syncthreads();
#pragma unroll
    for (int o = 1; o < 512; o <<= 1) {
        int t = (tx >= o) ? sh[tx - o] : 0;
        __syncthreads();
        sh[tx] += t;
        __syncthreads();
    }
    if (i < n) part[i] = sh[tx] - v;          // exclusive within block
    if (tx == 511) bsum[blockIdx.x] = sh[511];
}

__global__ void k_scan2(int* bsum, int nb) {
    __shared__ int sh[512];
    int tx = threadIdx.x;
    int v = (tx < nb) ? bsum[tx] : 0;
    sh[tx] = v;
    __syncthreads();
#pragma unroll
    for (int o = 1; o < 512; o <<= 1) {
        int t = (tx >= o) ? sh[tx - o] : 0;
        __syncthreads();
        sh[tx] += t;
        __syncthreads();
    }
    if (tx < nb) bsum[tx] = sh[tx] - v;       // exclusive
}

__global__ void k_scan3(const int* __restrict__ part, const int* __restrict__ bsum,
                        int* rows, int* cur, int n) {
    int i = blockIdx.x * blockDim.x + threadIdx.x;
    if (i < n) {
        int v = part[i] + bsum[i >> 9];
        rows[i] = v;
        cur[i] = v;
    }
}

__global__ void k_scatter(const int* __restrict__ src, const int* __restrict__ dst,
                          int* cur, int* csrc, int E) {
    int e = blockIdx.x * blockDim.x + threadIdx.x;
    if (e < E) {
        int slot = atomicAdd(&cur[dst[e]], 1);
        csrc[slot] = src[e];
    }
}

// ---------------- pad W4 (128x40 -> 128x64, zeros) ----------------
__global__ void k_pad_w4(const float* __restrict__ W4, float* W4p) {
    int t = blockIdx.x * blockDim.x + threadIdx.x;
    if (t < 128 * 64) {
        int k = t >> 6, c = t & 63;
        W4p[t] = (c < 40) ? W4[k * 40 + c] : 0.0f;
    }
}

// ---------------- GEMM: Y[N,NCOL] = (relu?)X[N,128] @ W[128,NCOL], f32x2 ----------
template <int NCOL, bool RELU>
__global__ void __launch_bounds__(256, 2)
k_gemm(const float* __restrict__ X, const float* __restrict__ W,
       float* __restrict__ Y, int Nrows) {
    constexpr int CG = NCOL / 8;      // threads along N
    constexpr int RG = 256 / CG;      // threads along M
    constexpr int TILE_M = RG * 8;
    __shared__ float xs[TILE_M * 32];
    __shared__ float ws[32 * NCOL];

    int tid = threadIdx.x;
    int tc = tid % CG;
    int tr = tid / CG;
    int c0 = tc * 8;
    int rowBase = blockIdx.x * TILE_M;

    unsigned long long acc[8][4];     // [row i][col pair j2], packed f32x2
#pragma unroll
    for (int i = 0; i < 8; ++i)
#pragma unroll
        for (int j = 0; j < 4; ++j) acc[i][j] = 0ULL;

    for (int k0 = 0; k0 < 128; k0 += 32) {
        for (int idx = tid; idx < 32 * NCOL; idx += 256)
            ws[idx] = W[k0 * NCOL + idx];
        constexpr int NF4 = TILE_M * 8;
#pragma unroll
        for (int j = 0; j < NF4 / 256; ++j) {
            int fi = tid + j * 256;
            int row = fi >> 3, kq = fi & 7;
            int gr = rowBase + row;
            float4 v = make_float4(0.f, 0.f, 0.f, 0.f);
            if (gr < Nrows)
                v = *(const float4*)&X[(size_t)gr * 128 + k0 + kq * 4];
            if (RELU) {
                v.x = fmaxf(v.x, 0.f); v.y = fmaxf(v.y, 0.f);
                v.z = fmaxf(v.z, 0.f); v.w = fmaxf(v.w, 0.f);
            }
            *(float4*)&xs[row * 32 + kq * 4] = v;
        }
        __syncthreads();
#pragma unroll
        for (int kk = 0; kk < 32; ++kk) {
            // B column pairs, packed directly from smem (8B aligned)
            const unsigned long long* wp =
                (const unsigned long long*)&ws[kk * NCOL + c0];
            unsigned long long bp[4];
#pragma unroll
            for (int j = 0; j < 4; ++j) bp[j] = wp[j];
            // A scalars duplicated into packed form
#pragma unroll
            for (int i = 0; i < 8; ++i) {
                float a = xs[(tr * 8 + i) * 32 + kk];
                unsigned long long ad;
                DUP2(ad, a);
#pragma unroll
                for (int j = 0; j < 4; ++j) FFMA2(acc[i][j], ad, bp[j]);
            }
        }
        __syncthreads();
    }
#pragma unroll
    for (int i = 0; i < 8; ++i) {
        int gr = rowBase + tr * 8 + i;
        if (gr < Nrows) {
            unsigned lo0, hi0, lo1, hi1, lo2, hi2, lo3, hi3;
            UNPK2(lo0, hi0, acc[i][0]);
            UNPK2(lo1, hi1, acc[i][1]);
            UNPK2(lo2, hi2, acc[i][2]);
            UNPK2(lo3, hi3, acc[i][3]);
            float4 o0 = make_float4(__uint_as_float(lo0), __uint_as_float(hi0),
                                    __uint_as_float(lo1), __uint_as_float(hi1));
            float4 o1 = make_float4(__uint_as_float(lo2), __uint_as_float(hi2),
                                    __uint_as_float(lo3), __uint_as_float(hi3));
            *(float4*)&Y[(size_t)gr * NCOL + c0] = o0;
            *(float4*)&Y[(size_t)gr * NCOL + c0 + 4] = o1;
        }
    }
}

// ---------------- fused aggregation, width 128: one warp per node ----------------
template <bool RELU, bool DUAL>
__global__ void k_aggf128(const float* __restrict__ H, const float* __restrict__ b,
                          const float* __restrict__ dinv,
                          const int* __restrict__ rows, const int* __restrict__ cnt,
                          const int* __restrict__ csrc,
                          float* __restrict__ OUT, float* __restrict__ OUT2, int N) {
    int node = (blockIdx.x * blockDim.x + threadIdx.x) >> 5;
    int lane = threadIdx.x & 31;
    if (node >= N) return;
    float di = dinv[node];
    float sn = di * di;
    float4 h = *(const float4*)&H[(size_t)node * 128 + lane * 4];
    float4 bv = ((const float4*)b)[lane];
    float4 acc = make_float4(fmaf(sn, h.x, bv.x), fmaf(sn, h.y, bv.y),
                             fmaf(sn, h.z, bv.z), fmaf(sn, h.w, bv.w));
    int beg = rows[node];
    int m = cnt[node];
    for (int bo = 0; bo < m; bo += 32) {
        int k = min(32, m - bo);
        int s = 0; float dj = 0.f;
        if (bo + lane < m) {
            s = csrc[beg + bo + lane];
            dj = dinv[s] * di;
        }
        for (int j = 0; j < k; ++j) {
            int ss = __shfl_sync(0xffffffffu, s, j);
            float nrm = __shfl_sync(0xffffffffu, dj, j);
            float4 v = *(const float4*)&H[(size_t)ss * 128 + lane * 4];
            acc.x = fmaf(nrm, v.x, acc.x);
            acc.y = fmaf(nrm, v.y, acc.y);
            acc.z = fmaf(nrm, v.z, acc.z);
            acc.w = fmaf(nrm, v.w, acc.w);
        }
    }
    if (RELU) {
        acc.x = fmaxf(acc.x, 0.f); acc.y = fmaxf(acc.y, 0.f);
        acc.z = fmaxf(acc.z, 0.f); acc.w = fmaxf(acc.w, 0.f);
    }
    *(float4*)&OUT[(size_t)node * 128 + lane * 4] = acc;
    if (DUAL)
        *(float4*)&OUT2[(size_t)node * 128 + lane * 4] = acc;
}

// ---------------- fused aggregation, width 40 (H stride 64) -> d_out -------------
__global__ void k_aggf40(const float* __restrict__ H64, const float* __restrict__ b4,
                         const float* __restrict__ dinv,
                         const int* __restrict__ rows, const int* __restrict__ cnt,
                         const int* __restrict__ csrc,
                         float* __restrict__ OUT, int N) {
    int node = (blockIdx.x * blockDim.x + threadIdx.x) >> 5;
    int lane = threadIdx.x & 31;
    if (node >= N) return;
    float di = dinv[node];
    float sn = di * di;
    float4 acc = make_float4(0.f, 0.f, 0.f, 0.f);
    if (lane < 10) {
        float4 h = *(const float4*)&H64[(size_t)node * 64 + lane * 4];
        float4 bv = ((const float4*)b4)[lane];
        acc = make_float4(fmaf(sn, h.x, bv.x), fmaf(sn, h.y, bv.y),
                          fmaf(sn, h.z, bv.z), fmaf(sn, h.w, bv.w));
    }
    int beg = rows[node];
    int m = cnt[node];
    for (int bo = 0; bo < m; bo += 32) {
        int k = min(32, m - bo);
        int s = 0; float dj = 0.f;
        if (bo + lane < m) {
            s = csrc[beg + bo + lane];
            dj = dinv[s] * di;
        }
        for (int j = 0; j < k; ++j) {
            int ss = __shfl_sync(0xffffffffu, s, j);
            float nrm = __shfl_sync(0xffffffffu, dj, j);
            if (lane < 10) {
                float4 v = *(const float4*)&H64[(size_t)ss * 64 + lane * 4];
                acc.x = fmaf(nrm, v.x, acc.x);
                acc.y = fmaf(nrm, v.y, acc.y);
                acc.z = fmaf(nrm, v.z, acc.z);
                acc.w = fmaf(nrm, v.w, acc.w);
            }
        }
    }
    if (lane < 10)
        *(float4*)&OUT[(size_t)node * 40 + lane * 4] = acc;
}

// ---------------------------------------------------------------------------
extern "C" void kernel_launch(void* const* d_in, const int* in_sizes, int n_in,
                              void* d_out, int out_size) {
    const float* x   = (const float*)d_in[0];
    const int*   ei  = (const int*)d_in[1];
    const float* W1  = (const float*)d_in[2];
    const float* b1  = (const float*)d_in[3];
    const float* W2  = (const float*)d_in[4];
    const float* b2  = (const float*)d_in[5];
    const float* W3  = (const float*)d_in[6];
    const float* b3  = (const float*)d_in[7];
    const float* W4  = (const float*)d_in[8];
    const float* b4  = (const float*)d_in[9];
    float* out = (float*)d_out;

    int N = in_sizes[0] / 128;
    int E = in_sizes[1] / 2;
    const int* src = ei;
    const int* dst = ei + E;

    float *bufA, *bufB, *dinv, *W4p;
    int *cnt, *rows, *cur, *bsum, *csrc;
    cudaGetSymbolAddress((void**)&bufA, g_bufA);
    cudaGetSymbolAddress((void**)&bufB, g_bufB);
    cudaGetSymbolAddress((void**)&dinv, g_dinv);
    cudaGetSymbolAddress((void**)&W4p,  g_W4p);
    cudaGetSymbolAddress((void**)&cnt,  g_cnt);
    cudaGetSymbolAddress((void**)&rows, g_rows);
    cudaGetSymbolAddress((void**)&cur,  g_cur);
    cudaGetSymbolAddress((void**)&bsum, g_bsum);
    cudaGetSymbolAddress((void**)&csrc, g_csrc);

    int nb = (N + 511) / 512;

    // ---- CSR build + dinv ----
    k_zero_int<<<(N + 255) / 256, 256>>>(cnt, N);
    k_deg_int<<<(E + 255) / 256, 256>>>(dst, cnt, E);
    k_dinv<<<(N + 255) / 256, 256>>>(cnt, dinv, N);
    k_scan1<<<nb, 512>>>(cnt, rows, bsum, N);     // rows = per-block exclusive (temp)
    k_scan2<<<1, 512>>>(bsum, nb);
    k_scan3<<<(N + 255) / 256, 256>>>(rows, bsum, rows, cur, N);
    k_scatter<<<(E + 255) / 256, 256>>>(src, dst, cur, csrc, E);
    k_pad_w4<<<(128 * 64 + 255) / 256, 256>>>(W4, W4p);

    int gemm128_blocks = (N + 127) / 128;
    int gemm64_blocks  = (N + 255) / 256;
    int agg_blocks     = (N * 32 + 255) / 256;   // one warp per node

    // Layer 1
    k_gemm<128, false><<<gemm128_blocks, 256>>>(x, W1, bufA, N);
    k_aggf128<false, false><<<agg_blocks, 256>>>(bufA, b1, dinv, rows, cnt, csrc, bufB, nullptr, N);
    // Layer 2 (relu folded into GEMM input load)
    k_gemm<128, true><<<gemm128_blocks, 256>>>(bufB, W2, bufA, N);
    k_aggf128<false, false><<<agg_blocks, 256>>>(bufA, b2, dinv, rows, cnt, csrc, bufB, nullptr, N);
    // Layer 3 (agg applies relu, writes both latent output and GEMM4 input)
    k_gemm<128, true><<<gemm128_blocks, 256>>>(bufB, W3, bufA, N);
    k_aggf128<true, true><<<agg_blocks, 256>>>(bufA, b3, dinv, rows, cnt, csrc, bufB,
                                               out + (size_t)N * 40, N);
    // Layer 4: GEMM to padded 64-wide (input already relu'd), then 40-wide agg
    k_gemm<64, false><<<gemm64_blocks, 256>>>(bufB, W4p, bufA, N);
    k_aggf40<<<agg_blocks, 256>>>(bufA, b4, dinv, rows, cnt, csrc, out, N);
}

// round 7
// speedup vs baseline: 2.1619x; 1.3593x over previous
#include <cuda_runtime.h>
#include <cuda_bf16.h>
#include <cstdint>

// ---------------------------------------------------------------------------
// GCN 4 layers. Per layer: h = X@W ; out_i = b + dinv_i^2*h_i + sum_e nrm_e*h[src_e]
// CSR built per launch. Aggregation fused with bias/self-loop/relu (no atomics).
// GEMM via warp-level HMMA (mma.sync m16n8k16 bf16 — family-common PTX, works on
// plain compute_103): fp32 emulated as bf16 hi/lo split, 3 products, fp32 acc.
// Outputs: d_out[0:N*40] = logits, d_out[N*40:+N*128] = relu(layer3 agg).
// ---------------------------------------------------------------------------

#define N_NODES 100000
#define N_EDGES 1600000

__device__ float g_bufA[(size_t)N_NODES * 128];   // GEMM output h
__device__ float g_bufB[(size_t)N_NODES * 128];   // aggregation output
__device__ float g_dinv[N_NODES];
__device__ int   g_cnt[N_NODES];
__device__ int   g_rows[N_NODES];
__device__ int   g_cur[N_NODES];
__device__ int   g_bsum[512];
__device__ int   g_csrc[N_EDGES];
// W transposed to [n][k] bf16 hi/lo: W1,W2,W3 at 128x128, W4 padded to 64x128
#define WOFF2 (128 * 128)
#define WOFF3 (2 * 128 * 128)
#define WOFF4 (3 * 128 * 128)
#define WTOT  (3 * 128 * 128 + 64 * 128)
__device__ __align__(16) __nv_bfloat16 g_Bhi[WTOT];
__device__ __align__(16) __nv_bfloat16 g_Blo[WTOT];

// ---------------- mma / ldmatrix helpers ----------------
__device__ __forceinline__ void ldsm4(uint32_t* r, uint32_t addr) {
    asm volatile("ldmatrix.sync.aligned.m8n8.x4.shared.b16 {%0,%1,%2,%3}, [%4];"
                 : "=r"(r[0]), "=r"(r[1]), "=r"(r[2]), "=r"(r[3]) : "r"(addr));
}
__device__ __forceinline__ void mma_bf16(float* d, const uint32_t* a, const uint32_t* b) {
    asm volatile(
        "mma.sync.aligned.m16n8k16.row.col.f32.bf16.bf16.f32 "
        "{%0,%1,%2,%3},{%4,%5,%6,%7},{%8,%9},{%0,%1,%2,%3};"
        : "+f"(d[0]), "+f"(d[1]), "+f"(d[2]), "+f"(d[3])
        : "r"(a[0]), "r"(a[1]), "r"(a[2]), "r"(a[3]), "r"(b[0]), "r"(b[1]));
}
// pack two fp32 -> bf16x2 word (lower half = first arg)
__device__ __forceinline__ uint32_t pack_bf16(float lo_val, float hi_val) {
    uint32_t r;
    asm("cvt.rn.bf16x2.f32 %0, %1, %2;" : "=r"(r) : "f"(hi_val), "f"(lo_val));
    return r;
}

// ============================ CSR build ====================================
__global__ void k_zero_int(int* p, int n) {
    int i = blockIdx.x * blockDim.x + threadIdx.x;
    if (i < n) p[i] = 0;
}
__global__ void k_deg_int(const int* __restrict__ dst, int* cnt, int E) {
    int e = blockIdx.x * blockDim.x + threadIdx.x;
    if (e < E) atomicAdd(&cnt[dst[e]], 1);
}
__global__ void k_scan1(const int* __restrict__ cnt, int* part, int* bsum, int n) {
    __shared__ int sh[512];
    int tx = threadIdx.x;
    int i = blockIdx.x * 512 + tx;
    int v = (i < n) ? cnt[i] : 0;
    sh[tx] = v;
    __syncthreads();
#pragma unroll
    for (int o = 1; o < 512; o <<= 1) {
        int t = (tx >= o) ? sh[tx - o] : 0;
        __syncthreads();
        sh[tx] += t;
        __syncthreads();
    }
    if (i < n) part[i] = sh[tx] - v;
    if (tx == 511) bsum[blockIdx.x] = sh[511];
}
__global__ void k_scan2(int* bsum, int nb) {
    __shared__ int sh[512];
    int tx = threadIdx.x;
    int v = (tx < nb) ? bsum[tx] : 0;
    sh[tx] = v;
    __syncthreads();
#pragma unroll
    for (int o = 1; o < 512; o <<= 1) {
        int t = (tx >= o) ? sh[tx - o] : 0;
        __syncthreads();
        sh[tx] += t;
        __syncthreads();
    }
    if (tx < nb) bsum[tx] = sh[tx] - v;
}
// rows/cur from scan parts; also dinv from cnt (fused)
__global__ void k_scan3(const int* __restrict__ part, const int* __restrict__ bsum,
                        const int* __restrict__ cnt,
                        int* rows, int* cur, float* dinv, int n) {
    int i = blockIdx.x * blockDim.x + threadIdx.x;
    if (i < n) {
        int v = part[i] + bsum[i >> 9];
        rows[i] = v;
        cur[i] = v;
        dinv[i] = rsqrtf((float)cnt[i] + 1.0f);   // +1 self loop
    }
}
__global__ void k_scatter(const int* __restrict__ src, const int* __restrict__ dst,
                          int* cur, int* csrc, int E) {
    int e = blockIdx.x * blockDim.x + threadIdx.x;
    if (e < E) {
        int slot = atomicAdd(&cur[dst[e]], 1);
        csrc[slot] = src[e];
    }
}

// -------- W conversion (all 4): [k][NCOL] fp32 -> [n][128] bf16 hi/lo ------
__global__ void k_convW_all(const float* __restrict__ W1, const float* __restrict__ W2,
                            const float* __restrict__ W3, const float* __restrict__ W4,
                            __nv_bfloat16* __restrict__ Bhi, __nv_bfloat16* __restrict__ Blo) {
    int t = blockIdx.x * blockDim.x + threadIdx.x;
    if (t >= WTOT) return;
    const float* W;
    int NCOL, local;
    if (t < WOFF2)       { W = W1; NCOL = 128; local = t; }
    else if (t < WOFF3)  { W = W2; NCOL = 128; local = t - WOFF2; }
    else if (t < WOFF4)  { W = W3; NCOL = 128; local = t - WOFF3; }
    else                 { W = W4; NCOL = 40;  local = t - WOFF4; }
    int n = local >> 7, k = local & 127;
    float v = (n < NCOL) ? W[k * NCOL + n] : 0.0f;
    __nv_bfloat16 hi = __float2bfloat16(v);
    Bhi[t] = hi;
    Blo[t] = __float2bfloat16(v - __bfloat162float(hi));
}

// ========== HMMA GEMM: Y[N,NMMA] = (relu?)X[N,128] @ W[128,NMMA] ===========
// CTA: 128 rows x NMMA cols, 8 warps. Warp tile: 64 x (NMMA/4).
// K in 4 chunks of 32. A converted to bf16 hi/lo in smem (80B row stride,
// conflict-free ldmatrix). W pre-transposed [n][k] bf16 hi/lo in global.
template <int NMMA, bool RELU>
__global__ void __launch_bounds__(256, 2)
k_gemm_mma(const float* __restrict__ X,
           const __nv_bfloat16* __restrict__ WBhi,
           const __nv_bfloat16* __restrict__ WBlo,
           float* __restrict__ Y, int Nrows) {
    constexpr int WN = NMMA / 4;     // warp tile n width (32 or 16)
    constexpr int NT = WN / 8;       // n-tiles per warp (4 or 2)
    constexpr int NP = WN / 16;      // ldmatrix n-pairs (2 or 1)

    __shared__ __align__(16) __nv_bfloat16 As_hi[128 * 40];
    __shared__ __align__(16) __nv_bfloat16 As_lo[128 * 40];
    __shared__ __align__(16) __nv_bfloat16 Bs_hi[NMMA * 40];
    __shared__ __align__(16) __nv_bfloat16 Bs_lo[NMMA * 40];

    int tid = threadIdx.x;
    int lane = tid & 31;
    int w = tid >> 5;
    int warpM = w >> 2;              // 0..1
    int warpN = w & 3;               // 0..3
    int rowBase = blockIdx.x * 128;

    // per-lane ldmatrix addressing parts
    int lrow = (lane & 7) + ((lane >> 3) & 1) * 8;
    int lkb  = (lane >> 4) * 16;     // byte offset within k for col-half

    uint32_t a_hi_b = (uint32_t)__cvta_generic_to_shared(As_hi);
    uint32_t a_lo_b = (uint32_t)__cvta_generic_to_shared(As_lo);
    uint32_t b_hi_b = (uint32_t)__cvta_generic_to_shared(Bs_hi);
    uint32_t b_lo_b = (uint32_t)__cvta_generic_to_shared(Bs_lo);

    float acc[4][NT][4];
#pragma unroll
    for (int m = 0; m < 4; ++m)
#pragma unroll
        for (int nt = 0; nt < NT; ++nt)
#pragma unroll
            for (int j = 0; j < 4; ++j) acc[m][nt][j] = 0.0f;

    for (int chunk = 0; chunk < 4; ++chunk) {
        int k0 = chunk * 32;
        // ---- stage A: 128 rows x 32 k, fp32 -> bf16 hi/lo ----
#pragma unroll
        for (int i = 0; i < 4; ++i) {
            int idx = tid + i * 256;           // 1024 float4 tasks
            int row = idx >> 3, q = idx & 7;
            int gr = rowBase + row;
            float4 v = make_float4(0.f, 0.f, 0.f, 0.f);
            if (gr < Nrows)
                v = *(const float4*)&X[(size_t)gr * 128 + k0 + q * 4];
            if (RELU) {
                v.x = fmaxf(v.x, 0.f); v.y = fmaxf(v.y, 0.f);
                v.z = fmaxf(v.z, 0.f); v.w = fmaxf(v.w, 0.f);
            }
            uint2 hp, lp;
            hp.x = pack_bf16(v.x, v.y);
            hp.y = pack_bf16(v.z, v.w);
            // residuals: bf16 -> f32 is a 16-bit shift
            float h0 = __uint_as_float(hp.x << 16);
            float h1 = __uint_as_float(hp.x & 0xffff0000u);
            float h2 = __uint_as_float(hp.y << 16);
            float h3 = __uint_as_float(hp.y & 0xffff0000u);
            lp.x = pack_bf16(v.x - h0, v.y - h1);
            lp.y = pack_bf16(v.z - h2, v.w - h3);
            *(uint2*)(As_hi + row * 40 + q * 4) = hp;
            *(uint2*)(As_lo + row * 40 + q * 4) = lp;
        }
        // ---- stage B: NMMA n-rows x 32 k from pre-converted global ----
#pragma unroll
        for (int i = 0; i < NMMA / 32; ++i) {
            int idx = tid + i * 256;           // NMMA*8 uint2 tasks
            int row = idx >> 3, q = idx & 7;
            int gi = row * 32 + (k0 >> 2) + q; // uint2 index into [n][128]
            *(uint2*)(Bs_hi + row * 40 + q * 4) = ((const uint2*)WBhi)[gi];
            *(uint2*)(Bs_lo + row * 40 + q * 4) = ((const uint2*)WBlo)[gi];
        }
        __syncthreads();

#pragma unroll
        for (int ks = 0; ks < 2; ++ks) {
            int kb = ks * 32 + lkb;
            // B fragments for this k-step
            uint32_t bhi[NT][2], blo[NT][2];
#pragma unroll
            for (int p = 0; p < NP; ++p) {
                int brow = warpN * WN + p * 16 + lrow;
                uint32_t r[4];
                ldsm4(r, b_hi_b + brow * 80 + kb);
                bhi[2 * p][0] = r[0]; bhi[2 * p + 1][0] = r[1];
                bhi[2 * p][1] = r[2]; bhi[2 * p + 1][1] = r[3];
                ldsm4(r, b_lo_b + brow * 80 + kb);
                blo[2 * p][0] = r[0]; blo[2 * p + 1][0] = r[1];
                blo[2 * p][1] = r[2]; blo[2 * p + 1][1] = r[3];
            }
#pragma unroll
            for (int m = 0; m < 4; ++m) {
                int arow = warpM * 64 + m * 16 + lrow;
                uint32_t ahi[4], alo[4];
                ldsm4(ahi, a_hi_b + arow * 80 + kb);
                ldsm4(alo, a_lo_b + arow * 80 + kb);
#pragma unroll
                for (int nt = 0; nt < NT; ++nt) {
                    mma_bf16(acc[m][nt], ahi, bhi[nt]);
                    mma_bf16(acc[m][nt], ahi, blo[nt]);
                    mma_bf16(acc[m][nt], alo, bhi[nt]);
                }
            }
        }
        __syncthreads();
    }

    // ---- epilogue: fp32 stores (float2 per fragment row) ----
#pragma unroll
    for (int m = 0; m < 4; ++m) {
        int r = rowBase + warpM * 64 + m * 16 + (lane >> 2);
#pragma unroll
        for (int nt = 0; nt < NT; ++nt) {
            int c = warpN * WN + nt * 8 + (lane & 3) * 2;
            if (r < Nrows)
                *(float2*)&Y[(size_t)r * NMMA + c] =
                    make_float2(acc[m][nt][0], acc[m][nt][1]);
            if (r + 8 < Nrows)
                *(float2*)&Y[(size_t)(r + 8) * NMMA + c] =
                    make_float2(acc[m][nt][2], acc[m][nt][3]);
        }
    }
}

// ---------------- fused aggregation, width 128: one warp per node ----------------
template <bool RELU, bool DUAL>
__global__ void k_aggf128(const float* __restrict__ H, const float* __restrict__ b,
                          const float* __restrict__ dinv,
                          const int* __restrict__ rows, const int* __restrict__ cnt,
                          const int* __restrict__ csrc,
                          float* __restrict__ OUT, float* __restrict__ OUT2, int N) {
    int node = (blockIdx.x * blockDim.x + threadIdx.x) >> 5;
    int lane = threadIdx.x & 31;
    if (node >= N) return;
    float di = dinv[node];
    float sn = di * di;
    float4 h = *(const float4*)&H[(size_t)node * 128 + lane * 4];
    float4 bv = ((const float4*)b)[lane];
    float4 acc = make_float4(fmaf(sn, h.x, bv.x), fmaf(sn, h.y, bv.y),
                             fmaf(sn, h.z, bv.z), fmaf(sn, h.w, bv.w));
    int beg = rows[node];
    int m = cnt[node];
    for (int bo = 0; bo < m; bo += 32) {
        int k = min(32, m - bo);
        int s = 0; float dj = 0.f;
        if (bo + lane < m) {
            s = csrc[beg + bo + lane];
            dj = dinv[s] * di;
        }
        for (int j = 0; j < k; ++j) {
            int ss = __shfl_sync(0xffffffffu, s, j);
            float nrm = __shfl_sync(0xffffffffu, dj, j);
            float4 v = *(const float4*)&H[(size_t)ss * 128 + lane * 4];
            acc.x = fmaf(nrm, v.x, acc.x);
            acc.y = fmaf(nrm, v.y, acc.y);
            acc.z = fmaf(nrm, v.z, acc.z);
            acc.w = fmaf(nrm, v.w, acc.w);
        }
    }
    if (RELU) {
        acc.x = fmaxf(acc.x, 0.f); acc.y = fmaxf(acc.y, 0.f);
        acc.z = fmaxf(acc.z, 0.f); acc.w = fmaxf(acc.w, 0.f);
    }
    *(float4*)&OUT[(size_t)node * 128 + lane * 4] = acc;
    if (DUAL)
        *(float4*)&OUT2[(size_t)node * 128 + lane * 4] = acc;
}

// ---------------- fused aggregation, width 40 (H stride 64) -> d_out -------------
__global__ void k_aggf40(const float* __restrict__ H64, const float* __restrict__ b4,
                         const float* __restrict__ dinv,
                         const int* __restrict__ rows, const int* __restrict__ cnt,
                         const int* __restrict__ csrc,
                         float* __restrict__ OUT, int N) {
    int node = (blockIdx.x * blockDim.x + threadIdx.x) >> 5;
    int lane = threadIdx.x & 31;
    if (node >= N) return;
    float di = dinv[node];
    float sn = di * di;
    float4 acc = make_float4(0.f, 0.f, 0.f, 0.f);
    if (lane < 10) {
        float4 h = *(const float4*)&H64[(size_t)node * 64 + lane * 4];
        float4 bv = ((const float4*)b4)[lane];
        acc = make_float4(fmaf(sn, h.x, bv.x), fmaf(sn, h.y, bv.y),
                          fmaf(sn, h.z, bv.z), fmaf(sn, h.w, bv.w));
    }
    int beg = rows[node];
    int m = cnt[node];
    for (int bo = 0; bo < m; bo += 32) {
        int k = min(32, m - bo);
        int s = 0; float dj = 0.f;
        if (bo + lane < m) {
            s = csrc[beg + bo + lane];
            dj = dinv[s] * di;
        }
        for (int j = 0; j < k; ++j) {
            int ss = __shfl_sync(0xffffffffu, s, j);
            float nrm = __shfl_sync(0xffffffffu, dj, j);
            if (lane < 10) {
                float4 v = *(const float4*)&H64[(size_t)ss * 64 + lane * 4];
                acc.x = fmaf(nrm, v.x, acc.x);
                acc.y = fmaf(nrm, v.y, acc.y);
                acc.z = fmaf(nrm, v.z, acc.z);
                acc.w = fmaf(nrm, v.w, acc.w);
            }
        }
    }
    if (lane < 10)
        *(float4*)&OUT[(size_t)node * 40 + lane * 4] = acc;
}

// ---------------------------------------------------------------------------
extern "C" void kernel_launch(void* const* d_in, const int* in_sizes, int n_in,
                              void* d_out, int out_size) {
    const float* x   = (const float*)d_in[0];
    const int*   ei  = (const int*)d_in[1];
    const float* W1  = (const float*)d_in[2];
    const float* b1  = (const float*)d_in[3];
    const float* W2  = (const float*)d_in[4];
    const float* b2  = (const float*)d_in[5];
    const float* W3  = (const float*)d_in[6];
    const float* b3  = (const float*)d_in[7];
    const float* W4  = (const float*)d_in[8];
    const float* b4  = (const float*)d_in[9];
    float* out = (float*)d_out;

    int N = in_sizes[0] / 128;
    int E = in_sizes[1] / 2;
    const int* src = ei;
    const int* dst = ei + E;

    float *bufA, *bufB, *dinv;
    int *cnt, *rows, *cur, *bsum, *csrc;
    __nv_bfloat16 *Bhi, *Blo;
    cudaGetSymbolAddress((void**)&bufA, g_bufA);
    cudaGetSymbolAddress((void**)&bufB, g_bufB);
    cudaGetSymbolAddress((void**)&dinv, g_dinv);
    cudaGetSymbolAddress((void**)&cnt,  g_cnt);
    cudaGetSymbolAddress((void**)&rows, g_rows);
    cudaGetSymbolAddress((void**)&cur,  g_cur);
    cudaGetSymbolAddress((void**)&bsum, g_bsum);
    cudaGetSymbolAddress((void**)&csrc, g_csrc);
    cudaGetSymbolAddress((void**)&Bhi,  g_Bhi);
    cudaGetSymbolAddress((void**)&Blo,  g_Blo);

    int nb = (N + 511) / 512;
    int gemm_blocks = (N + 127) / 128;
    int agg_blocks  = (N * 32 + 255) / 256;

    // Launch order chosen so ncu (-s 5 -c 1) captures the layer-1 GEMM.
    k_convW_all<<<(WTOT + 255) / 256, 256>>>(W1, W2, W3, W4, Bhi, Blo);   // 0
    k_zero_int<<<(N + 255) / 256, 256>>>(cnt, N);                         // 1
    k_deg_int<<<(E + 255) / 256, 256>>>(dst, cnt, E);                     // 2
    k_scan1<<<nb, 512>>>(cnt, rows, bsum, N);                             // 3
    k_scan2<<<1, 512>>>(bsum, nb);                                        // 4
    k_gemm_mma<128, false><<<gemm_blocks, 256>>>(x, Bhi, Blo, bufA, N);   // 5 <- ncu
    k_scan3<<<(N + 255) / 256, 256>>>(rows, bsum, cnt, rows, cur, dinv, N);
    k_scatter<<<(E + 255) / 256, 256>>>(src, dst, cur, csrc, E);

    // Layer 1 aggregation
    k_aggf128<false, false><<<agg_blocks, 256>>>(bufA, b1, dinv, rows, cnt, csrc, bufB, nullptr, N);
    // Layer 2 (relu folded into GEMM A conversion)
    k_gemm_mma<128, true><<<gemm_blocks, 256>>>(bufB, Bhi + WOFF2, Blo + WOFF2, bufA, N);
    k_aggf128<false, false><<<agg_blocks, 256>>>(bufA, b2, dinv, rows, cnt, csrc, bufB, nullptr, N);
    // Layer 3 (agg applies relu, writes latent output + GEMM4 input)
    k_gemm_mma<128, true><<<gemm_blocks, 256>>>(bufB, Bhi + WOFF3, Blo + WOFF3, bufA, N);
    k_aggf128<true, true><<<agg_blocks, 256>>>(bufA, b3, dinv, rows, cnt, csrc, bufB,
                                               out + (size_t)N * 40, N);
    // Layer 4: GEMM to padded 64-wide (input already relu'd), then 40-wide agg
    k_gemm_mma<64, false><<<gemm_blocks, 256>>>(bufB, Bhi + WOFF4, Blo + WOFF4, bufA, N);
    k_aggf40<<<agg_blocks, 256>>>(bufA, b4, dinv, rows, cnt, csrc, out, N);
}